// round 13
// baseline (speedup 1.0000x reference)
#include <cuda_runtime.h>
#include <stdint.h>

// Shapes (fixed by the problem)
#define BATCH 32
#define SEQ   4096
#define VOCAB 10
#define FEAT  1024
#define DIM   64

#define CHUNK   256
#define THREADS 256
#define NCTAS   (BATCH * (SEQ / CHUNK))    // 512 CTAs (all wave-1 resident)
#define NPROD   80                         // producing CTAs (8 pairs each)
#define NPAIRS  (DIM * VOCAB)              // 640

// Projected table P[d][v] + producer counter (reset by a graph memset node)
__device__ float    g_P[NPAIRS];
__device__ unsigned g_pdone;

__device__ __forceinline__ unsigned ld_acquire(const unsigned* p) {
    unsigned v;
    asm volatile("ld.acquire.gpu.global.u32 %0, [%1];" : "=r"(v) : "l"(p));
    return v;
}

// ---------------------------------------------------------------------------
// Single fused kernel, 512 CTAs.
//   CTAs 0..79: warps 0..7 each compute one (d,v) pair (8 pairs/CTA, 640
//               total), publish with ONE CTA-level atomic, then gather.
//   All CTAs:   prefetch indices, wait for g_pdone==80, load sP, gather.
// No in-kernel reset: g_pdone is zeroed by a memset node preceding this
// kernel in the captured graph, so every replay starts clean.
// ---------------------------------------------------------------------------
__global__ void __launch_bounds__(THREADS)
fused_kernel(const int* __restrict__ idx,
             const float* __restrict__ fp,
             const float* __restrict__ W,
             const float* __restrict__ bias,
             float* __restrict__ out) {
    __shared__ float sP[NPAIRS];

    const int tid  = threadIdx.x;
    const int bid  = blockIdx.x;
    const int wid  = tid >> 5;
    const int lane = tid & 31;

    const int b  = bid >> 4;               // 16 chunks per batch row
    const int l0 = (bid & 15) * CHUNK;
    const int lq = tid & 63;               // float4 slot (fixed per thread)
    const int db = tid >> 6;               // base d-row (0..3)

    // P-independent prefetch: this thread's 4 vocab indices (coalesced 16B)
    int4 iv = *reinterpret_cast<const int4*>(idx + b * SEQ + l0 + lq * 4);

    // ----- production (CTAs 0..79, one pair per warp) -----
    if (bid < NPROD) {
        const int pid = bid * 8 + wid;      // 0..639
        const int d = pid / VOCAB;
        const int v = pid - d * VOCAB;

        const float4* fr = reinterpret_cast<const float4*>(fp + v * FEAT);
        const float4* wr = reinterpret_cast<const float4*>(W  + d * FEAT);

        float s = 0.f;
#pragma unroll
        for (int f = lane; f < FEAT / 4; f += 32) {   // 8 iters, 16 LDG.128
            float4 a = fr[f];
            float4 c = wr[f];
            s += a.x * c.x + a.y * c.y + a.z * c.z + a.w * c.w;
        }
#pragma unroll
        for (int o = 16; o > 0; o >>= 1)
            s += __shfl_down_sync(0xffffffffu, s, o);

        if (lane == 0)
            g_P[pid] = s + bias[d];

        __syncthreads();                    // all 8 pairs of this CTA done
        if (tid == 0) {
            __threadfence();                // publish g_P rows
            atomicAdd(&g_pdone, 1u);        // 80 atomics total (cheap)
        }
    }

    // ----- wait for all producers -----
    if (tid == 0) {
        while (ld_acquire(&g_pdone) < NPROD) __nanosleep(64);
    }
    __syncthreads();

    // Table into shared: [d][v]
    for (int i = tid; i < NPAIRS; i += THREADS)
        sP[i] = g_P[i];
    __syncthreads();

    // ----- gather: 64 conflict-free LDS + 16 coalesced STG.128 per thread --
    float* ob = out + (b * DIM) * SEQ + l0 + lq * 4;
#pragma unroll
    for (int k = 0; k < 16; k++) {
        const int d = db + 4 * k;
        const float* p = &sP[d * VOCAB];
        float4 r;
        r.x = p[iv.x];
        r.y = p[iv.y];
        r.z = p[iv.z];
        r.w = p[iv.w];
        *reinterpret_cast<float4*>(ob + d * SEQ) = r;
    }
}

// ---------------------------------------------------------------------------
// Graph per launch: [memset g_pdone = 0] -> [fused_kernel]. Both nodes are
// capture-legal (async memset, no allocation). Deterministic across replays.
// Inputs per metadata order: indices (int32), fp_table (f32), W (f32), b (f32)
// ---------------------------------------------------------------------------
extern "C" void kernel_launch(void* const* d_in, const int* in_sizes, int n_in,
                              void* d_out, int out_size) {
    const int*   idx  = (const int*)d_in[0];
    const float* fp   = (const float*)d_in[1];
    const float* W    = (const float*)d_in[2];
    const float* bias = (const float*)d_in[3];
    float*       out  = (float*)d_out;

    void* pdone_addr = nullptr;
    cudaGetSymbolAddress(&pdone_addr, g_pdone);
    cudaMemsetAsync(pdone_addr, 0, sizeof(unsigned), 0);

    fused_kernel<<<NCTAS, THREADS>>>(idx, fp, W, bias, out);
}